// round 2
// baseline (speedup 1.0000x reference)
#include <cuda_runtime.h>
#include <cuda_bf16.h>
#include <math.h>

// Problem constants
#define B_SZ   2
#define T_SEQ  2048
#define C_DIM  1024
#define C3     3072
#define NH     16
#define DH     64
#define MEMLEN 1024

#define M_TOT  (B_SZ * T_SEQ)   // 4096

// Scratch (no cudaMalloc allowed). NOTE: referenced ONLY from device code —
// taking a __device__ symbol's address in host code is invalid.
__device__ float g_qkv[(size_t)M_TOT * C3];   // 48 MB
__device__ float g_y[(size_t)M_TOT * C_DIM];  // 16 MB

// ----------------------------------------------------------------------------
// fp32 NT GEMM: C[M,N] = A[M,K] * B[N,K]^T
// 128x128 block tile, BK=8, 256 threads, 8x8 register microtile.
// ----------------------------------------------------------------------------
__device__ __forceinline__ void gemm_nt_body(
    const float* __restrict__ A, const float* __restrict__ Bm,
    float* __restrict__ C, int M, int N, int K)
{
    const int BM = 128, BN = 128, BK = 8;
    __shared__ float As[BK][BM];
    __shared__ float Bs[BK][BN];

    int tid = threadIdx.x;
    int tx = tid & 15;        // 0..15 (N direction)
    int ty = tid >> 4;        // 0..15 (M direction)
    int m0 = blockIdx.y * BM;
    int n0 = blockIdx.x * BN;

    int lrow = tid >> 1;          // 0..127
    int lseg = (tid & 1) * 4;     // 0 or 4

    float acc[8][8];
#pragma unroll
    for (int i = 0; i < 8; i++)
#pragma unroll
        for (int j = 0; j < 8; j++) acc[i][j] = 0.0f;

    const float* aptr = A + (size_t)(m0 + lrow) * K + lseg;
    const float* bptr = Bm + (size_t)(n0 + lrow) * K + lseg;

    for (int k0 = 0; k0 < K; k0 += BK) {
        float4 av = *(const float4*)(aptr + k0);
        float4 bv = *(const float4*)(bptr + k0);
        As[lseg + 0][lrow] = av.x; As[lseg + 1][lrow] = av.y;
        As[lseg + 2][lrow] = av.z; As[lseg + 3][lrow] = av.w;
        Bs[lseg + 0][lrow] = bv.x; Bs[lseg + 1][lrow] = bv.y;
        Bs[lseg + 2][lrow] = bv.z; Bs[lseg + 3][lrow] = bv.w;
        __syncthreads();

#pragma unroll
        for (int kk = 0; kk < BK; kk++) {
            float a[8], b[8];
            float4 a0 = *(const float4*)&As[kk][ty * 8];
            float4 a1 = *(const float4*)&As[kk][ty * 8 + 4];
            float4 b0 = *(const float4*)&Bs[kk][tx * 8];
            float4 b1 = *(const float4*)&Bs[kk][tx * 8 + 4];
            a[0]=a0.x; a[1]=a0.y; a[2]=a0.z; a[3]=a0.w;
            a[4]=a1.x; a[5]=a1.y; a[6]=a1.z; a[7]=a1.w;
            b[0]=b0.x; b[1]=b0.y; b[2]=b0.z; b[3]=b0.w;
            b[4]=b1.x; b[5]=b1.y; b[6]=b1.z; b[7]=b1.w;
#pragma unroll
            for (int i = 0; i < 8; i++)
#pragma unroll
                for (int j = 0; j < 8; j++)
                    acc[i][j] = fmaf(a[i], b[j], acc[i][j]);
        }
        __syncthreads();
    }

#pragma unroll
    for (int i = 0; i < 8; i++) {
        float* crow = C + (size_t)(m0 + ty * 8 + i) * N + n0 + tx * 8;
#pragma unroll
        for (int j = 0; j < 8; j++) crow[j] = acc[i][j];
    }
}

__global__ __launch_bounds__(256)
void gemm_qkv_kernel(const float* __restrict__ x, const float* __restrict__ w)
{
    gemm_nt_body(x, w, g_qkv, M_TOT, C3, C_DIM);
}

__global__ __launch_bounds__(256)
void gemm_proj_kernel(const float* __restrict__ w, float* __restrict__ out)
{
    gemm_nt_body(g_y, w, out, M_TOT, C_DIM, C_DIM);
}

// ----------------------------------------------------------------------------
// Fused flash attention (fp32).
// grid: (T/64 q-tiles, NH heads, B batches). 256 threads.
// Q tile = 64 rows, KV tile = 64 rows, dh = 64.
// mask: attend iff (col <= row) || (col < MEMLEN)  -> computed analytically.
// Writes g_y directly (device-side symbol).
// ----------------------------------------------------------------------------
#define BQ 64
#define BKV 64
#define SPAD 65   // row stride padding

__global__ __launch_bounds__(256)
void attn_kernel(const float* __restrict__ qm)
{
    int qt = blockIdx.x, h = blockIdx.y, b = blockIdx.z;
    int q0 = qt * BQ;
    int tid = threadIdx.x;
    int tx = tid & 15;    // key-col direction (4 cols each)
    int ty = tid >> 4;    // query-row direction (4 rows each)

    extern __shared__ float sm[];
    float* Qs = sm;                         // [BQ][SPAD]
    float* Ks = Qs + BQ * SPAD;             // [BKV][SPAD]
    float* Vs = Ks + BKV * SPAD;            // [BKV][SPAD]
    float* Ss = Vs + BKV * SPAD;            // [BQ][SPAD]
    float* mrow = Ss + BQ * SPAD;           // [BQ]
    float* lrow = mrow + BQ;                // [BQ]
    float* frow = lrow + BQ;                // [BQ]
    float* qscale = frow + BQ;              // [DH]

    if (tid < DH) qscale[tid] = logf((float)T_SEQ) * qm[tid] * rsqrtf((float)DH);
    if (tid < BQ) { mrow[tid] = -1e30f; lrow[tid] = 0.0f; }
    __syncthreads();

    // Load + scale Q tile
    const float* qbase = g_qkv + (size_t)(b * T_SEQ + q0) * C3 + h * DH;
    for (int idx = tid; idx < BQ * DH; idx += 256) {
        int r = idx >> 6, d = idx & 63;
        Qs[r * SPAD + d] = qbase[(size_t)r * C3 + d] * qscale[d];
    }
    __syncthreads();

    float acc[4][4];
#pragma unroll
    for (int i = 0; i < 4; i++)
#pragma unroll
        for (int j = 0; j < 4; j++) acc[i][j] = 0.0f;

    int maxcol = (q0 + BQ > MEMLEN) ? (q0 + BQ) : MEMLEN;
    int nTiles = maxcol / BKV;

    for (int t = 0; t < nTiles; t++) {
        int kj0 = t * BKV;
        const float* kbase = g_qkv + (size_t)(b * T_SEQ + kj0) * C3 + C_DIM + h * DH;
        const float* vbase = kbase + C_DIM;
        for (int idx = tid; idx < BKV * DH; idx += 256) {
            int r = idx >> 6, d = idx & 63;
            Ks[r * SPAD + d] = kbase[(size_t)r * C3 + d];
            Vs[r * SPAD + d] = vbase[(size_t)r * C3 + d];
        }
        __syncthreads();

        // S = Q K^T (64x64), thread computes 4x4
        float s[4][4];
#pragma unroll
        for (int i = 0; i < 4; i++)
#pragma unroll
            for (int j = 0; j < 4; j++) s[i][j] = 0.0f;

#pragma unroll 4
        for (int d = 0; d < DH; d++) {
            float qr[4], kc[4];
#pragma unroll
            for (int i = 0; i < 4; i++) qr[i] = Qs[(ty * 4 + i) * SPAD + d];
#pragma unroll
            for (int j = 0; j < 4; j++) kc[j] = Ks[(tx * 4 + j) * SPAD + d];
#pragma unroll
            for (int i = 0; i < 4; i++)
#pragma unroll
                for (int j = 0; j < 4; j++)
                    s[i][j] = fmaf(qr[i], kc[j], s[i][j]);
        }

        bool needMask = (kj0 + BKV > MEMLEN);
#pragma unroll
        for (int i = 0; i < 4; i++) {
#pragma unroll
            for (int j = 0; j < 4; j++) {
                float v = s[i][j];
                if (needMask) {
                    int grow = q0 + ty * 4 + i;
                    int gcol = kj0 + tx * 4 + j;
                    if (gcol >= MEMLEN && gcol > grow) v = -1e30f;
                }
                Ss[(ty * 4 + i) * SPAD + tx * 4 + j] = v;
            }
        }
        __syncthreads();

        // Online softmax: 4 threads per row, 16 cols each
        {
            int row = tid >> 2, part = tid & 3;
            float* srow = Ss + row * SPAD + part * 16;
            float mx = -1e30f;
#pragma unroll
            for (int c = 0; c < 16; c++) mx = fmaxf(mx, srow[c]);
            mx = fmaxf(mx, __shfl_xor_sync(0xffffffffu, mx, 1));
            mx = fmaxf(mx, __shfl_xor_sync(0xffffffffu, mx, 2));
            float mold = mrow[row];
            float mnew = fmaxf(mold, mx);
            float fac = __expf(mold - mnew);
            float lsum = 0.0f;
#pragma unroll
            for (int c = 0; c < 16; c++) {
                float p = __expf(srow[c] - mnew);
                srow[c] = p;
                lsum += p;
            }
            lsum += __shfl_xor_sync(0xffffffffu, lsum, 1);
            lsum += __shfl_xor_sync(0xffffffffu, lsum, 2);
            if (part == 0) {
                mrow[row] = mnew;
                lrow[row] = lrow[row] * fac + lsum;
                frow[row] = fac;
            }
        }
        __syncthreads();

        // O = O*fac + P @ V
        float fi[4];
#pragma unroll
        for (int i = 0; i < 4; i++) fi[i] = frow[ty * 4 + i];
#pragma unroll
        for (int i = 0; i < 4; i++)
#pragma unroll
            for (int j = 0; j < 4; j++) acc[i][j] *= fi[i];

#pragma unroll 4
        for (int kk = 0; kk < BKV; kk++) {
            float pv[4], vv[4];
#pragma unroll
            for (int i = 0; i < 4; i++) pv[i] = Ss[(ty * 4 + i) * SPAD + kk];
#pragma unroll
            for (int j = 0; j < 4; j++) vv[j] = Vs[kk * SPAD + tx * 4 + j];
#pragma unroll
            for (int i = 0; i < 4; i++)
#pragma unroll
                for (int j = 0; j < 4; j++)
                    acc[i][j] = fmaf(pv[i], vv[j], acc[i][j]);
        }
        __syncthreads();
    }

    // Write y in [B,T,C] layout (heads interleaved back): y[b, q, h*DH + d]
#pragma unroll
    for (int i = 0; i < 4; i++) {
        float inv = 1.0f / lrow[ty * 4 + i];
        float* yrow = g_y + (size_t)(b * T_SEQ + q0 + ty * 4 + i) * C_DIM + h * DH + tx * 4;
#pragma unroll
        for (int j = 0; j < 4; j++) yrow[j] = acc[i][j] * inv;
    }
}

// ----------------------------------------------------------------------------
// Launch
// ----------------------------------------------------------------------------
static const int ATTN_SMEM =
    (BQ * SPAD + BKV * SPAD + BKV * SPAD + BQ * SPAD + 3 * BQ + DH) * (int)sizeof(float);

extern "C" void kernel_launch(void* const* d_in, const int* in_sizes, int n_in,
                              void* d_out, int out_size)
{
    const float* x      = (const float*)d_in[0];
    const float* w_qkv  = (const float*)d_in[1];
    const float* w_proj = (const float*)d_in[2];
    const float* qm     = (const float*)d_in[3];
    float* out = (float*)d_out;

    static bool attr_set = false;
    if (!attr_set) {
        cudaFuncSetAttribute(attn_kernel,
                             cudaFuncAttributeMaxDynamicSharedMemorySize, ATTN_SMEM);
        attr_set = true;
    }

    // GEMM1: qkv = x @ w_qkv^T  (4096 x 3072 x 1024)
    {
        dim3 grid(C3 / 128, M_TOT / 128);
        gemm_qkv_kernel<<<grid, 256>>>(x, w_qkv);
    }

    // Fused attention -> g_y
    {
        dim3 grid(T_SEQ / BQ, NH, B_SZ);
        attn_kernel<<<grid, 256, ATTN_SMEM>>>(qm);
    }

    // GEMM2: out = y @ w_proj^T  (4096 x 1024 x 1024)
    {
        dim3 grid(C_DIM / 128, M_TOT / 128);
        gemm_proj_kernel<<<grid, 256>>>(w_proj, out);
    }
}